// round 6
// baseline (speedup 1.0000x reference)
#include <cuda_runtime.h>
#include <cuda_fp16.h>

// B=512, L=1000, H=128. 2-layer LSTM + linear head via mma.sync, 2 phases/step.
// 64 CTAs x 512 threads (16 warps); CTA owns 8 batches (full n8 of m16n8k16).
// Gate-interleaved row order: warp wp's mtile pair = all 4 gates for hidden
// j in [8wp, 8wp+8): mtileA rows = i(0-7)|f(8-15), mtileB = g|o.
// => mma D-frags hold i,f,g,o for (j = 8wp+(lane>>2), batches 2(lane&3), +1):
//    activations run on registers; gates never touch smem.
// Pipelined: PhaseB computes gates2(t) AND gates1(t+1) (both need only h1(t),
// h2(t-1)); PhaseA does ACT2(t-1)+ACT1(t)+head. 2 __syncthreads per step.
// w_hh1: smem frags. w_hh2: even mtile in regs, odd mtile in smem.
// w_ih2: streamed from L2 via 4-slot rotating LDG prefetch.

__device__ uint4 g_w1f[8192];    // w_hh1 frags (gate-interleaved rows)
__device__ uint4 g_w2af[8192];   // w_ih2 frags
__device__ uint4 g_w2bf[8192];   // w_hh2 frags
__device__ float g_b1[512];      // b_ih1 + b_hh1
__device__ float g_b2[512];      // b_ih2 + b_hh2

__device__ __forceinline__ void mma16816(float& d0, float& d1, float& d2, float& d3,
                                         uint4 a, uint2 b) {
    asm volatile(
        "mma.sync.aligned.m16n8k16.row.col.f32.f16.f16.f32 "
        "{%0,%1,%2,%3},{%4,%5,%6,%7},{%8,%9},{%0,%1,%2,%3};"
        : "+f"(d0), "+f"(d1), "+f"(d2), "+f"(d3)
        : "r"(a.x), "r"(a.y), "r"(a.z), "r"(a.w), "r"(b.x), "r"(b.y));
}
__device__ __forceinline__ float sigf(float v) {
    return __fdividef(1.f, 1.f + __expf(-v));
}
__device__ __forceinline__ float tanh_f(float v) {
    return 2.f * __fdividef(1.f, 1.f + __expf(-2.f * v)) - 1.f;
}

// frag r = mt*256 + kt*32 + lane ; wp=mt>>1, pair=mt&1, g=lane>>2, t4=lane&3
// row0 = (pair*2)*128 + wp*8 + g   (gates i or g)
// row1 = (pair*2+1)*128 + wp*8 + g (gates f or o)
// k0 = kt*16 + 2*t4 ; a-frag: {row0,k0..k0+1},{row1,k0..},{row0,k0+8..},{row1,k0+8..}
__global__ void prep_kernel(const float* __restrict__ w_hh1,
                            const float* __restrict__ w_ih2,
                            const float* __restrict__ w_hh2,
                            const float* __restrict__ b_ih1,
                            const float* __restrict__ b_hh1,
                            const float* __restrict__ b_ih2,
                            const float* __restrict__ b_hh2) {
    int idx = blockIdx.x * blockDim.x + threadIdx.x;
    if (idx < 512) {
        g_b1[idx] = b_ih1[idx] + b_hh1[idx];
        g_b2[idx] = b_ih2[idx] + b_hh2[idx];
    }
    if (idx < 3 * 8192) {
        int mat = idx >> 13;
        int r = idx & 8191;
        int mt = r >> 8, kt = (r >> 5) & 7, lane = r & 31;
        int wp = mt >> 1, pair = mt & 1;
        int g = lane >> 2, t4 = lane & 3;
        int row0 = (pair * 2) * 128 + wp * 8 + g;
        int row1 = (pair * 2 + 1) * 128 + wp * 8 + g;
        int k0 = kt * 16 + 2 * t4;
        const float* W = (mat == 0) ? w_hh1 : (mat == 1) ? w_ih2 : w_hh2;
        uint4* dst = (mat == 0) ? g_w1f : (mat == 1) ? g_w2af : g_w2bf;
        __half2 p;
        uint4 v;
        p = __floats2half2_rn(W[row0 * 128 + k0],     W[row0 * 128 + k0 + 1]); v.x = *(unsigned*)&p;
        p = __floats2half2_rn(W[row1 * 128 + k0],     W[row1 * 128 + k0 + 1]); v.y = *(unsigned*)&p;
        p = __floats2half2_rn(W[row0 * 128 + k0 + 8], W[row0 * 128 + k0 + 9]); v.z = *(unsigned*)&p;
        p = __floats2half2_rn(W[row1 * 128 + k0 + 8], W[row1 * 128 + k0 + 9]); v.w = *(unsigned*)&p;
        dst[r] = v;
    }
}

// smem map (bytes)
#define OFF_W1    0        // uint4[8192]  w_hh1 frags           131072
#define OFF_W2B   131072   // uint4[4096]  w_hh2 odd-mtile frags  65536
#define OFF_H1F   196608   // half[1024]   h1 B-frag layout        2048
#define OFF_H2F   198656   // half[1024]   h2 B-frag layout        2048
#define OFF_PS    200704   // float[128]   head partials            512
#define SMEM_TOTAL 201216

__global__ void __launch_bounds__(512, 1)
lstm_main(const float* __restrict__ x, const float* __restrict__ w_ih1,
          const float* __restrict__ w_lin, const float* __restrict__ b_lin,
          float* __restrict__ out) {
    extern __shared__ char smch[];
    uint4* sw1  = reinterpret_cast<uint4*>(smch + OFF_W1);
    uint4* sw2b = reinterpret_cast<uint4*>(smch + OFF_W2B);
    uint2* h1fp = reinterpret_cast<uint2*>(smch + OFF_H1F);
    uint2* h2fp = reinterpret_cast<uint2*>(smch + OFF_H2F);
    __half* h1h = reinterpret_cast<__half*>(smch + OFF_H1F);
    __half* h2h = reinterpret_cast<__half*>(smch + OFF_H2F);
    float* ps   = reinterpret_cast<float*>(smch + OFF_PS);

    const int tid = threadIdx.x;
    const int lane = tid & 31;
    const int wp = tid >> 5;
    const int dg = lane >> 2;       // hidden offset within warp's 8
    const int tt = lane & 3;        // batch pair selector
    const int j = wp * 8 + dg;      // this thread's hidden index
    const int b0c = blockIdx.x * 8;
    const int bA = b0c + 2 * tt, bB = bA + 1;

    // ---- one-time smem fills ----
    for (int i = tid; i < 8192; i += 512) sw1[i] = g_w1f[i];
    for (int i = tid; i < 4096; i += 512) {
        int w2 = i >> 8, kt = (i >> 5) & 7, ln = i & 31;
        sw2b[i] = g_w2bf[(2 * w2 + 1) * 256 + kt * 32 + ln];
    }
    for (int i = tid; i < 1024; i += 512)
        reinterpret_cast<unsigned*>(smch + OFF_H1F)[i] = 0;  // zero h1f+h2f

    // resident w_hh2 even-mtile frags
    uint4 rw[8];
#pragma unroll
    for (int kt = 0; kt < 8; kt++) rw[kt] = g_w2bf[(2 * wp) * 256 + kt * 32 + lane];

    const int fiA = (2 * wp) * 256 + lane;       // + kt*32
    const int fiB = (2 * wp + 1) * 256 + lane;

    // per-thread gate constants (hidden j)
    const float b1i = g_b1[j],       b1f = g_b1[128 + j];
    const float b1g = g_b1[256 + j], b1o = g_b1[384 + j];
    const float wii = w_ih1[j],       wif = w_ih1[128 + j];
    const float wig = w_ih1[256 + j], wio = w_ih1[384 + j];
    const float b2i = g_b2[j],       b2f = g_b2[128 + j];
    const float b2g = g_b2[256 + j], b2o = g_b2[384 + j];
    const float wl = w_lin[j];
    const float bl = b_lin[0];

    // h B-frag half-offsets for (j, colA/colB)
    const int hkt = j >> 4, hkk = j & 15;
    const int hreg = hkk >> 3, htt = (hkk >> 1) & 3, hhalf = hkk & 1;
    const int offA = ((hkt * 32 + (2 * tt) * 4 + htt) * 2 + hreg) * 2 + hhalf;
    const int offB = ((hkt * 32 + (2 * tt + 1) * 4 + htt) * 2 + hreg) * 2 + hhalf;

    float c1a = 0.f, c1b = 0.f, c2a = 0.f, c2b = 0.f;
    float xn0 = x[bA * 1000], xn1 = x[bB * 1000];

    // accumulators: layer1 gates(t+1) [A=i/f, B=g/o], layer2 gates(t)
    float l1a0 = 0.f, l1a1 = 0.f, l1a2 = 0.f, l1a3 = 0.f;
    float l1b0 = 0.f, l1b1 = 0.f, l1b2 = 0.f, l1b3 = 0.f;
    float l2a0 = 0.f, l2a1 = 0.f, l2a2 = 0.f, l2a3 = 0.f;
    float l2b0 = 0.f, l2b1 = 0.f, l2b2 = 0.f, l2b3 = 0.f;

    // 4-slot rotating w_ih2 prefetch; bootstrap with mtA kt0..3
    uint4 bufA[4];
#pragma unroll
    for (int q = 0; q < 4; q++) bufA[q] = g_w2af[fiA + q * 32];

    __syncthreads();

#pragma unroll 1
    for (int t = 0; t < 1000; t++) {
        // ================= Phase A: activations (registers only) =============
        float xa = xn0, xb = xn1;
        if (t < 999) { xn0 = x[bA * 1000 + t + 1]; xn1 = x[bB * 1000 + t + 1]; }

        if (t > 0) {
            // ACT2(t-1): gates in l2a/l2b
            float iA = sigf(l2a0 + b2i), iB = sigf(l2a1 + b2i);
            float fA = sigf(l2a2 + b2f), fB = sigf(l2a3 + b2f);
            float gA = tanh_f(l2b0 + b2g), gB = tanh_f(l2b1 + b2g);
            float oA = sigf(l2b2 + b2o), oB = sigf(l2b3 + b2o);
            c2a = fA * c2a + iA * gA;
            c2b = fB * c2b + iB * gB;
            float h2a = oA * tanh_f(c2a), h2b = oB * tanh_f(c2b);
            h2h[offA] = __float2half_rn(h2a);
            h2h[offB] = __float2half_rn(h2b);
            float p0 = wl * h2a, p1 = wl * h2b;
#pragma unroll
            for (int off = 4; off <= 16; off <<= 1) {
                p0 += __shfl_xor_sync(0xffffffffu, p0, off);
                p1 += __shfl_xor_sync(0xffffffffu, p1, off);
            }
            if (lane < 4)
                *reinterpret_cast<float2*>(ps + wp * 8 + 2 * tt) = make_float2(p0, p1);
        }
        {
            // ACT1(t): gates in l1a/l1b (+ bias + w_ih1*x)
            float iA = sigf(l1a0 + b1i + wii * xa), iB = sigf(l1a1 + b1i + wii * xb);
            float fA = sigf(l1a2 + b1f + wif * xa), fB = sigf(l1a3 + b1f + wif * xb);
            float gA = tanh_f(l1b0 + b1g + wig * xa), gB = tanh_f(l1b1 + b1g + wig * xb);
            float oA = sigf(l1b2 + b1o + wio * xa), oB = sigf(l1b3 + b1o + wio * xb);
            c1a = fA * c1a + iA * gA;
            c1b = fB * c1b + iB * gB;
            h1h[offA] = __float2half_rn(oA * tanh_f(c1a));
            h1h[offB] = __float2half_rn(oB * tanh_f(c1b));
        }
        __syncthreads();

        // ================= Phase B: fused matmuls ============================
        if (t > 0 && tid < 8) {
            float s = 0.f;
#pragma unroll
            for (int w = 0; w < 16; w++) s += ps[w * 8 + tid];
            out[(b0c + tid) * 1000 + (t - 1)] = s + bl;
        }

        l1a0 = l1a1 = l1a2 = l1a3 = 0.f;
        l1b0 = l1b1 = l1b2 = l1b3 = 0.f;
        l2a0 = l2a1 = l2a2 = l2a3 = 0.f;
        l2b0 = l2b1 = l2b2 = l2b3 = 0.f;

#pragma unroll
        for (int kt = 0; kt < 8; kt++) {   // h1(t): w_hh1 (both mtiles) + w_ih2 mtA
            uint2 B1 = h1fp[kt * 32 + lane];
            mma16816(l1a0, l1a1, l1a2, l1a3, sw1[fiA + kt * 32], B1);
            mma16816(l1b0, l1b1, l1b2, l1b3, sw1[fiB + kt * 32], B1);
            mma16816(l2a0, l2a1, l2a2, l2a3, bufA[kt & 3], B1);
            bufA[kt & 3] = (kt < 4) ? g_w2af[fiA + (kt + 4) * 32]
                                    : g_w2af[fiB + (kt - 4) * 32];
        }
#pragma unroll
        for (int kt = 0; kt < 8; kt++) {   // h2(t-1): w_hh2 even(regs) + odd(smem)
            uint2 B2 = h2fp[kt * 32 + lane];
            mma16816(l2a0, l2a1, l2a2, l2a3, rw[kt], B2);
            mma16816(l2b0, l2b1, l2b2, l2b3, sw2b[wp * 256 + kt * 32 + lane], B2);
        }
#pragma unroll
        for (int kt = 0; kt < 8; kt++) {   // h1(t): w_ih2 mtB
            uint2 B1 = h1fp[kt * 32 + lane];
            mma16816(l2b0, l2b1, l2b2, l2b3, bufA[kt & 3], B1);
            bufA[kt & 3] = (kt < 4) ? g_w2af[fiB + (kt + 4) * 32]
                                    : g_w2af[fiA + (kt - 4) * 32];  // next step mtA
        }
        __syncthreads();
    }

    // ================= epilogue: ACT2(999) + head =================
    {
        float iA = sigf(l2a0 + b2i), iB = sigf(l2a1 + b2i);
        float fA = sigf(l2a2 + b2f), fB = sigf(l2a3 + b2f);
        float gA = tanh_f(l2b0 + b2g), gB = tanh_f(l2b1 + b2g);
        float oA = sigf(l2b2 + b2o), oB = sigf(l2b3 + b2o);
        c2a = fA * c2a + iA * gA;
        c2b = fB * c2b + iB * gB;
        float p0 = wl * (oA * tanh_f(c2a)), p1 = wl * (oB * tanh_f(c2b));
#pragma unroll
        for (int off = 4; off <= 16; off <<= 1) {
            p0 += __shfl_xor_sync(0xffffffffu, p0, off);
            p1 += __shfl_xor_sync(0xffffffffu, p1, off);
        }
        if (lane < 4)
            *reinterpret_cast<float2*>(ps + wp * 8 + 2 * tt) = make_float2(p0, p1);
    }
    __syncthreads();
    if (tid < 8) {
        float s = 0.f;
#pragma unroll
        for (int w = 0; w < 16; w++) s += ps[w * 8 + tid];
        out[(b0c + tid) * 1000 + 999] = s + bl;
    }
}

extern "C" void kernel_launch(void* const* d_in, const int* in_sizes, int n_in,
                              void* d_out, int out_size) {
    const float* x     = (const float*)d_in[0];
    const float* w_ih1 = (const float*)d_in[1];
    const float* w_hh1 = (const float*)d_in[2];
    const float* b_ih1 = (const float*)d_in[3];
    const float* b_hh1 = (const float*)d_in[4];
    const float* w_ih2 = (const float*)d_in[5];
    const float* w_hh2 = (const float*)d_in[6];
    const float* b_ih2 = (const float*)d_in[7];
    const float* b_hh2 = (const float*)d_in[8];
    const float* w_lin = (const float*)d_in[9];
    const float* b_lin = (const float*)d_in[10];
    float* out = (float*)d_out;

    cudaFuncSetAttribute(lstm_main, cudaFuncAttributeMaxDynamicSharedMemorySize, SMEM_TOTAL);

    prep_kernel<<<48, 512>>>(w_hh1, w_ih2, w_hh2, b_ih1, b_hh1, b_ih2, b_hh2);
    lstm_main<<<64, 512, SMEM_TOTAL>>>(x, w_ih1, w_lin, b_lin, out);
}

// round 8
// speedup vs baseline: 1.4362x; 1.4362x over previous
#include <cuda_runtime.h>
#include <cuda_fp16.h>

// B=512, L=1000, H=128. 2-layer LSTM + linear head via mma.sync tensor cores.
// 128 CTAs x 512 threads; CTA owns 4 batches (cols 0-3 of the m16n8k16 n-dim;
// cols 4-7 of the B fragments stay zero and their D outputs are never read).
// Warp w: gate rows [32w, 32w+32) = mtiles 2w, 2w+1.
// Weights fp16, pre-swizzled into mma A-fragment order by prep kernel.
// w_hh1: smem. w_hh2: even mtile in regs, odd mtile in smem. w_ih2: streamed
// from L2 with a full-phase-distance rotating 8-slot prefetch.
// Activations: MUFU.TANH (tanh.approx.f32); sigmoid(x)=0.5*tanh(0.5x)+0.5.
// Gates go through a stride-9 smem buffer; cell state fp32 in registers.

__device__ uint4 g_w1f[8192];    // w_hh1 frags
__device__ uint4 g_w2af[8192];   // w_ih2 frags
__device__ uint4 g_w2bf[8192];   // w_hh2 frags
__device__ float g_b1[512];      // b_ih1 + b_hh1
__device__ float g_b2[512];      // b_ih2 + b_hh2

__device__ __forceinline__ void mma16816(float& d0, float& d1, float& d2, float& d3,
                                         uint4 a, uint2 b) {
    asm volatile(
        "mma.sync.aligned.m16n8k16.row.col.f32.f16.f16.f32 "
        "{%0,%1,%2,%3},{%4,%5,%6,%7},{%8,%9},{%0,%1,%2,%3};"
        : "+f"(d0), "+f"(d1), "+f"(d2), "+f"(d3)
        : "r"(a.x), "r"(a.y), "r"(a.z), "r"(a.w), "r"(b.x), "r"(b.y));
}
__device__ __forceinline__ float tanhapx(float v) {
    float r; asm("tanh.approx.f32 %0, %1;" : "=f"(r) : "f"(v)); return r;
}
__device__ __forceinline__ float sigf(float v) {
    return fmaf(0.5f, tanhapx(0.5f * v), 0.5f);
}

__global__ void prep_kernel(const float* __restrict__ w_hh1,
                            const float* __restrict__ w_ih2,
                            const float* __restrict__ w_hh2,
                            const float* __restrict__ b_ih1,
                            const float* __restrict__ b_hh1,
                            const float* __restrict__ b_ih2,
                            const float* __restrict__ b_hh2) {
    int idx = blockIdx.x * blockDim.x + threadIdx.x;
    if (idx < 512) {
        g_b1[idx] = b_ih1[idx] + b_hh1[idx];
        g_b2[idx] = b_ih2[idx] + b_hh2[idx];
    }
    if (idx < 3 * 8192) {
        int mat = idx >> 13;
        int r = idx & 8191;
        int mt = r >> 8, kt = (r >> 5) & 7, lane = r & 31;
        int g = lane >> 2, t = lane & 3;
        int m0 = mt * 16 + g, m1 = m0 + 8;
        int k0 = kt * 16 + 2 * t;
        const float* W = (mat == 0) ? w_hh1 : (mat == 1) ? w_ih2 : w_hh2;
        uint4* dst = (mat == 0) ? g_w1f : (mat == 1) ? g_w2af : g_w2bf;
        __half2 p;
        uint4 v;
        p = __floats2half2_rn(W[m0 * 128 + k0],     W[m0 * 128 + k0 + 1]); v.x = *(unsigned*)&p;
        p = __floats2half2_rn(W[m1 * 128 + k0],     W[m1 * 128 + k0 + 1]); v.y = *(unsigned*)&p;
        p = __floats2half2_rn(W[m0 * 128 + k0 + 8], W[m0 * 128 + k0 + 9]); v.z = *(unsigned*)&p;
        p = __floats2half2_rn(W[m1 * 128 + k0 + 8], W[m1 * 128 + k0 + 9]); v.w = *(unsigned*)&p;
        dst[r] = v;
    }
}

// smem map (bytes)
#define OFF_W1    0        // uint4[8192]  w_hh1 frags           131072
#define OFF_W2B   131072   // uint4[4096]  w_hh2 odd-mtile frags  65536
#define OFF_GS    196608   // float[512*9] gate buffer            18432
#define OFF_H1F   215040   // half[1024]   h1 B-frag layout        2048
#define OFF_H2F   217088   // half[1024]   h2 B-frag layout        2048
#define OFF_PS    219136   // float[32]    head partials            128
#define SMEM_TOTAL 219264

__global__ void __launch_bounds__(512, 1)
lstm_main(const float* __restrict__ x, const float* __restrict__ w_ih1,
          const float* __restrict__ w_lin, const float* __restrict__ b_lin,
          float* __restrict__ out) {
    extern __shared__ char smch[];
    uint4* sw1   = reinterpret_cast<uint4*>(smch + OFF_W1);
    uint4* sw2b  = reinterpret_cast<uint4*>(smch + OFF_W2B);
    float* gs    = reinterpret_cast<float*>(smch + OFF_GS);
    uint2* h1fp  = reinterpret_cast<uint2*>(smch + OFF_H1F);
    uint2* h2fp  = reinterpret_cast<uint2*>(smch + OFF_H2F);
    __half* h1h  = reinterpret_cast<__half*>(smch + OFF_H1F);
    __half* h2h  = reinterpret_cast<__half*>(smch + OFF_H2F);
    float* ps    = reinterpret_cast<float*>(smch + OFF_PS);

    const int tid = threadIdx.x;
    const int lane = tid & 31;
    const int wp = tid >> 5;
    const int j = tid & 127;    // activation: hidden index
    const int bq = tid >> 7;    // activation: batch index (0..3) = frag col
    const int b0c = blockIdx.x * 4;

    // ---- one-time smem fills ----
    for (int i = tid; i < 8192; i += 512) sw1[i] = g_w1f[i];
    for (int i = tid; i < 4096; i += 512) {
        int w2 = i >> 8, kt = (i >> 5) & 7, ln = i & 31;
        sw2b[i] = g_w2bf[(2 * w2 + 1) * 256 + kt * 32 + ln];
    }
    for (int i = tid; i < 1024; i += 512)
        reinterpret_cast<unsigned*>(smch + OFF_H1F)[i] = 0;  // zeros h1f + h2f

    // resident w_hh2 even-mtile fragments
    uint4 rw[8];
#pragma unroll
    for (int kt = 0; kt < 8; kt++) rw[kt] = g_w2bf[(2 * wp) * 256 + kt * 32 + lane];

    // activation-role constants
    const float b10 = g_b1[j],       b11 = g_b1[128 + j];
    const float b12 = g_b1[256 + j], b13 = g_b1[384 + j];
    const float wg0 = w_ih1[j],       wg1 = w_ih1[128 + j];
    const float wg2 = w_ih1[256 + j], wg3 = w_ih1[384 + j];
    const float b20 = g_b2[j],       b21 = g_b2[128 + j];
    const float b22 = g_b2[256 + j], b23 = g_b2[384 + j];
    const float wl = w_lin[j];
    const float bl = b_lin[0];
    float c1a = 0.f, c2a = 0.f;
    float xn0 = x[(b0c + bq) * 1000];

    // h B-fragment store offset for (hidden j, frag col bq)
    const int hkt = j >> 4, hkk = j & 15;
    const int hreg = hkk >> 3, htt = (hkk >> 1) & 3, hhalf = hkk & 1;
    const int offA = ((hkt * 32 + bq * 4 + htt) * 2 + hreg) * 2 + hhalf;

    // matmul-role constants
    const int fi0 = (2 * wp) * 256 + lane;      // + kt*32
    const int fi1 = (2 * wp + 1) * 256 + lane;
    const int dg = lane >> 2, dt2 = (lane & 3) * 2;
    const int ra = 2 * wp * 16 + dg;            // D rows: ra, ra+8, ra+16, ra+24
    const int ja = j * 9 + bq;                  // activation gate-read base

    __syncthreads();

#pragma unroll 1
    for (int t = 0; t < 1000; t++) {
        // ================= MM1: gates1 = w_hh1 . h1  =================
        uint4 bufA[8];
#pragma unroll
        for (int kt = 0; kt < 8; kt++) bufA[kt] = g_w2af[fi0 + kt * 32];  // prefetch w_ih2 mt0

        float d00 = 0.f, d01 = 0.f, d02 = 0.f, d03 = 0.f;
        float d10 = 0.f, d11 = 0.f, d12 = 0.f, d13 = 0.f;
#pragma unroll
        for (int kt = 0; kt < 8; kt++) {
            uint2 B = h1fp[kt * 32 + lane];
            mma16816(d00, d01, d02, d03, sw1[fi0 + kt * 32], B);
            mma16816(d10, d11, d12, d13, sw1[fi1 + kt * 32], B);
        }
        gs[ra * 9 + dt2] = d00;        gs[ra * 9 + dt2 + 1] = d01;
        gs[(ra + 8) * 9 + dt2] = d02;  gs[(ra + 8) * 9 + dt2 + 1] = d03;
        gs[(ra + 16) * 9 + dt2] = d10; gs[(ra + 16) * 9 + dt2 + 1] = d11;
        gs[(ra + 24) * 9 + dt2] = d12; gs[(ra + 24) * 9 + dt2 + 1] = d13;
        __syncthreads();

        // ================= ACT1 =================
        {
            float xa = xn0;
            if (t < 999) xn0 = x[(b0c + bq) * 1000 + t + 1];
            float gi = gs[ja] + b10 + wg0 * xa;
            float gf = gs[ja + 1152] + b11 + wg1 * xa;
            float gg = gs[ja + 2304] + b12 + wg2 * xa;
            float go = gs[ja + 3456] + b13 + wg3 * xa;
            c1a = sigf(gf) * c1a + sigf(gi) * tanhapx(gg);
            h1h[offA] = __float2half_rn(sigf(go) * tanhapx(c1a));
        }
        __syncthreads();

        // ================= MM2: gates2 = w_ih2 . h1 + w_hh2 . h2 =================
        d00 = 0.f; d01 = 0.f; d02 = 0.f; d03 = 0.f;
        d10 = 0.f; d11 = 0.f; d12 = 0.f; d13 = 0.f;
#pragma unroll
        for (int kt = 0; kt < 8; kt++) {          // w_ih2 mt0 (buffered), refill with mt1
            uint2 B = h1fp[kt * 32 + lane];
            mma16816(d00, d01, d02, d03, bufA[kt], B);
            bufA[kt] = g_w2af[fi1 + kt * 32];
        }
#pragma unroll
        for (int kt = 0; kt < 8; kt++) {          // w_hh2 mt0 (resident regs)
            uint2 B = h2fp[kt * 32 + lane];
            mma16816(d00, d01, d02, d03, rw[kt], B);
        }
#pragma unroll
        for (int kt = 0; kt < 8; kt++) {          // w_hh2 mt1 (smem)
            uint2 B = h2fp[kt * 32 + lane];
            mma16816(d10, d11, d12, d13, sw2b[wp * 256 + kt * 32 + lane], B);
        }
#pragma unroll
        for (int kt = 0; kt < 8; kt++) {          // w_ih2 mt1 (buffered)
            uint2 B = h1fp[kt * 32 + lane];
            mma16816(d10, d11, d12, d13, bufA[kt], B);
        }
        gs[ra * 9 + dt2] = d00;        gs[ra * 9 + dt2 + 1] = d01;
        gs[(ra + 8) * 9 + dt2] = d02;  gs[(ra + 8) * 9 + dt2 + 1] = d03;
        gs[(ra + 16) * 9 + dt2] = d10; gs[(ra + 16) * 9 + dt2 + 1] = d11;
        gs[(ra + 24) * 9 + dt2] = d12; gs[(ra + 24) * 9 + dt2 + 1] = d13;
        __syncthreads();

        // ================= ACT2 + head =================
        {
            float gi = gs[ja] + b20;
            float gf = gs[ja + 1152] + b21;
            float gg = gs[ja + 2304] + b22;
            float go = gs[ja + 3456] + b23;
            c2a = sigf(gf) * c2a + sigf(gi) * tanhapx(gg);
            float h2a = sigf(go) * tanhapx(c2a);
            h2h[offA] = __float2half_rn(h2a);
            float p0 = wl * h2a;   // warp covers 32 j-values of batch bq
#pragma unroll
            for (int off = 16; off >= 1; off >>= 1)
                p0 += __shfl_xor_sync(0xffffffffu, p0, off);
            if (lane == 0) ps[wp] = p0;
        }
        __syncthreads();
        if (tid < 4)
            out[(b0c + tid) * 1000 + t] =
                ps[tid * 4] + ps[tid * 4 + 1] + ps[tid * 4 + 2] + ps[tid * 4 + 3] + bl;
    }
}

extern "C" void kernel_launch(void* const* d_in, const int* in_sizes, int n_in,
                              void* d_out, int out_size) {
    const float* x     = (const float*)d_in[0];
    const float* w_ih1 = (const float*)d_in[1];
    const float* w_hh1 = (const float*)d_in[2];
    const float* b_ih1 = (const float*)d_in[3];
    const float* b_hh1 = (const float*)d_in[4];
    const float* w_ih2 = (const float*)d_in[5];
    const float* w_hh2 = (const float*)d_in[6];
    const float* b_ih2 = (const float*)d_in[7];
    const float* b_hh2 = (const float*)d_in[8];
    const float* w_lin = (const float*)d_in[9];
    const float* b_lin = (const float*)d_in[10];
    float* out = (float*)d_out;

    cudaFuncSetAttribute(lstm_main, cudaFuncAttributeMaxDynamicSharedMemorySize, SMEM_TOTAL);

    prep_kernel<<<48, 512>>>(w_hh1, w_ih2, w_hh2, b_ih1, b_hh1, b_ih2, b_hh2);
    lstm_main<<<128, 512, SMEM_TOTAL>>>(x, w_ih1, w_lin, b_lin, out);
}